// round 14
// baseline (speedup 1.0000x reference)
#include <cuda_runtime.h>
#include <cstddef>
#include <cstdint>

// FusionAdjacency: Af = rownorm( sigmoid(g)*scatter(s) + (1-sigmoid(g))*scatter(t) )
//
// R11: concurrent TMA fill + L2-park fill.
//  K1 (one wave, homogeneous): per block, the elected thread grid-strides
//      cp.async.bulk 16KB zero-stores over rows [0,TROWS) (DRAM-paced, no SM
//      issue cost); ALL threads fold the hist REDs and plain-store-fill rows
//      [TROWS,NN) whose dirty lines PARK in the 126MB L2 (no DRAM writeback
//      during K1). DRAM never idles.
//  K2: rowinv = guarded reciprocal; re-zero rowsum (graph-replay safe).
//  K3: scatter all edges; park-region atomics are L2 hits; the 96MB parked
//      writeback drains underneath the latency-bound scatter.

#define NN     8192
#define TROWS  5120                                  // TMA region rows
#define STAGE  16384                                 // 16KB smem staging
#define TMA_BYTES ((long long)TROWS * NN * 4)        // 160 MB
#define NCHUNKS  ((int)(TMA_BYTES / STAGE))          // 10240

__device__ float g_rowsum[NN];  // zero at module load; K2 re-zeros each call
__device__ float g_rowinv[NN];

__device__ __forceinline__ uint32_t smem_u32(const void* p) {
    uint32_t a;
    asm("{ .reg .u64 t; cvta.to.shared.u64 t, %1; cvt.u32.u64 %0, t; }"
        : "=r"(a) : "l"(p));
    return a;
}

// ---------------------------------------------------------------- K1
__global__ __launch_bounds__(256) void k1_fill(
        const int* __restrict__ rows_s, const float* __restrict__ vals_s, int Es,
        const int* __restrict__ rows_t, const float* __restrict__ vals_t, int Et,
        const float* __restrict__ gamma, float* __restrict__ out) {
    __shared__ __align__(128) float4 stage[STAGE / 16];

    const int tid = blockIdx.x * blockDim.x + threadIdx.x;
    const int stride = gridDim.x * blockDim.x;
    const float4 z = make_float4(0.f, 0.f, 0.f, 0.f);

    // zero the 16KB staging buffer (1024 float4 / 256 threads = 4 each)
#pragma unroll
    for (int i = 0; i < 4; i++) stage[threadIdx.x + i * 256] = z;
    __syncthreads();
    asm volatile("fence.proxy.async.shared::cta;" ::: "memory");

    // (a) elected thread: grid-stride TMA bulk zero-stores over [0,TROWS)
    if (threadIdx.x == 0) {
        const uint32_t saddr = smem_u32(stage);
        char* gbase = reinterpret_cast<char*>(out);
        for (int ch = blockIdx.x; ch < NCHUNKS; ch += gridDim.x) {
            asm volatile(
                "cp.async.bulk.global.shared::cta.bulk_group [%0], [%1], %2;"
                :: "l"(gbase + (long long)ch * STAGE), "r"(saddr),
                   "r"((uint32_t)STAGE)
                : "memory");
        }
        asm volatile("cp.async.bulk.commit_group;" ::: "memory");
    }

    // (b) hist fold: fire-and-forget REDs into 32KB L2-hot region
    const float g = gamma[0];
    const float alpha = 1.0f / (1.0f + expf(-g));
    const float beta = 1.0f - alpha;
    for (int e = tid; e < Es; e += stride)
        atomicAdd(&g_rowsum[__ldg(&rows_s[e])], alpha * __ldg(&vals_s[e]));
    for (int e = tid; e < Et; e += stride)
        atomicAdd(&g_rowsum[__ldg(&rows_t[e])], beta * __ldg(&vals_t[e]));

    // (c) park fill: plain stores over rows [TROWS,NN) -> dirty lines stay
    //     in L2; writeback deferred past kernel end (drains under K3)
    {
        float4* out4 = reinterpret_cast<float4*>(out + (size_t)TROWS * NN);
        const int n4 = (NN - TROWS) * (NN / 4);
        for (int i = tid; i < n4; i += stride) out4[i] = z;
    }

    // ensure this block's bulk stores completed before retiring
    if (threadIdx.x == 0) {
        asm volatile("cp.async.bulk.wait_group 0;" ::: "memory");
    }
}

// ---------------------------------------------------------------- K2
__global__ void k2_finalize() {
    int i = blockIdx.x * blockDim.x + threadIdx.x;
    if (i < NN) {
        float s = g_rowsum[i];
        g_rowinv[i] = (s == 0.0f) ? 1.0f : (1.0f / s);
        g_rowsum[i] = 0.0f;   // ready for next graph replay
    }
}

// ---------------------------------------------------------------- K3
__global__ __launch_bounds__(256) void k3_scatter(
        const int* __restrict__ rows_s, const int* __restrict__ cols_s,
        const float* __restrict__ vals_s, int Es,
        const int* __restrict__ rows_t, const int* __restrict__ cols_t,
        const float* __restrict__ vals_t, int Et,
        const float* __restrict__ gamma, float* __restrict__ out) {
    const float g = gamma[0];
    const float alpha = 1.0f / (1.0f + expf(-g));
    const float beta = 1.0f - alpha;
    const int tid = blockIdx.x * blockDim.x + threadIdx.x;
    const int stride = gridDim.x * blockDim.x;

    const int n = (Es > Et) ? Es : Et;
    for (int e = tid; e < n; e += stride) {
        int rs = 0, cs = 0;  float vs = 0.0f;
        if (e < Es) {
            rs = __ldg(&rows_s[e]);
            cs = __ldg(&cols_s[e]);
            vs = __ldg(&vals_s[e]);
        }
        int rt = 0, ct = 0;  float vt = 0.0f;
        if (e < Et) {
            rt = __ldg(&rows_t[e]);
            ct = __ldg(&cols_t[e]);
            vt = __ldg(&vals_t[e]);
        }
        float invs = g_rowinv[rs];
        float invt = g_rowinv[rt];
        if (e < Es) atomicAdd(&out[((size_t)rs << 13) + cs], alpha * vs * invs);
        if (e < Et) atomicAdd(&out[((size_t)rt << 13) + ct], beta * vt * invt);
    }
}

// ---------------------------------------------------------------- launch
extern "C" void kernel_launch(void* const* d_in, const int* in_sizes, int n_in,
                              void* d_out, int out_size) {
    const int*   rows_s = (const int*)d_in[0];
    const int*   cols_s = (const int*)d_in[1];
    const float* vals_s = (const float*)d_in[2];
    const int*   rows_t = (const int*)d_in[3];
    const int*   cols_t = (const int*)d_in[4];
    const float* vals_t = (const float*)d_in[5];
    const float* gamma  = (const float*)d_in[6];
    float* out = (float*)d_out;

    const int Es = in_sizes[0];
    const int Et = in_sizes[3];

    // one full resident wave: 148 SMs x 8 blocks of 256 threads
    k1_fill<<<1184, 256>>>(rows_s, vals_s, Es, rows_t, vals_t, Et,
                           gamma, out);

    k2_finalize<<<(NN + 255) / 256, 256>>>();

    k3_scatter<<<1184, 256>>>(rows_s, cols_s, vals_s, Es,
                              rows_t, cols_t, vals_t, Et, gamma, out);
}

// round 16
// speedup vs baseline: 1.0650x; 1.0650x over previous
#include <cuda_runtime.h>
#include <cstddef>
#include <cstdint>

// FusionAdjacency: Af = rownorm( sigmoid(g)*scatter(s) + (1-sigmoid(g))*scatter(t) )
//
// R13 (= R12 with ptxas-legal park store): priority-separated concurrent fill.
//  K1: elected threads stream TMA bulk zero-stores over rows [0,TROWS)
//      tagged L2::evict_first (drain to DRAM, never evict the park);
//      all threads park rows [TROWS,NN) in L2 with
//      st.global.L2::evict_last.v4.b64 (32B stores, dirty lines pinned; L2 is
//      the coherence point so they may never need DRAM writeback);
//      hist folded (<=1 edge/thread/list fire-and-forget REDs).
//  K2: rowinv = guarded reciprocal; re-zero rowsum (graph-replay safe).
//  K3: scatter all edges; park-region atomics are L2 hits.

#define NN     8192
#define TROWS  5120                                  // TMA (evict_first) rows
#define STAGE  16384                                 // 16KB smem staging
#define TMA_BYTES ((long long)TROWS * NN * 4)        // 160 MB
#define NCHUNKS  ((int)(TMA_BYTES / STAGE))          // 10240

__device__ float g_rowsum[NN];  // zero at module load; K2 re-zeros each call
__device__ float g_rowinv[NN];

__device__ __forceinline__ uint32_t smem_u32(const void* p) {
    uint32_t a;
    asm("{ .reg .u64 t; cvta.to.shared.u64 t, %1; cvt.u32.u64 %0, t; }"
        : "=r"(a) : "l"(p));
    return a;
}

// ---------------------------------------------------------------- K1
__global__ __launch_bounds__(256) void k1_fill(
        const int* __restrict__ rows_s, const float* __restrict__ vals_s, int Es,
        const int* __restrict__ rows_t, const float* __restrict__ vals_t, int Et,
        const float* __restrict__ gamma, float* __restrict__ out) {
    __shared__ __align__(128) float4 stage[STAGE / 16];

    const int tid = blockIdx.x * blockDim.x + threadIdx.x;
    const int stride = gridDim.x * blockDim.x;
    const float4 z = make_float4(0.f, 0.f, 0.f, 0.f);

    // zero the staging buffer (1024 float4 / 256 threads = 4 each)
#pragma unroll
    for (int i = 0; i < 4; i++) stage[threadIdx.x + i * 256] = z;
    __syncthreads();
    asm volatile("fence.proxy.async.shared::cta;" ::: "memory");

    // (a) elected thread: TMA bulk zero-stores, L2::evict_first policy so
    //     these lines drain to DRAM without displacing the park region.
    if (threadIdx.x == 0) {
        uint64_t pol;
        asm volatile("createpolicy.fractional.L2::evict_first.b64 %0, 1.0;"
                     : "=l"(pol));
        const uint32_t saddr = smem_u32(stage);
        char* gbase = reinterpret_cast<char*>(out);
        for (int ch = blockIdx.x; ch < NCHUNKS; ch += gridDim.x) {
            asm volatile(
                "cp.async.bulk.global.shared::cta.bulk_group.L2::cache_hint"
                " [%0], [%1], %2, %3;"
                :: "l"(gbase + (long long)ch * STAGE), "r"(saddr),
                   "r"((uint32_t)STAGE), "l"(pol)
                : "memory");
        }
        asm volatile("cp.async.bulk.commit_group;" ::: "memory");
    }

    // (b) hist fold: fire-and-forget REDs into 32KB L2-hot region
    const float g = gamma[0];
    const float alpha = 1.0f / (1.0f + expf(-g));
    const float beta = 1.0f - alpha;
    for (int e = tid; e < Es; e += stride)
        atomicAdd(&g_rowsum[__ldg(&rows_s[e])], alpha * __ldg(&vals_s[e]));
    for (int e = tid; e < Et; e += stride)
        atomicAdd(&g_rowsum[__ldg(&rows_t[e])], beta * __ldg(&vals_t[e]));

    // (c) park fill: 32B evict_last stores over rows [TROWS,NN) -> dirty
    //     lines pinned in L2; writeback deferred/avoided (L2 = coherence pt).
    {
        float* base = out + (size_t)TROWS * NN;
        const int n8 = (NN - TROWS) * (NN / 8);   // 32-byte units
        const unsigned long long z64 = 0ull;
        for (int i = tid; i < n8; i += stride) {
            float* p = base + (size_t)i * 8;
            asm volatile(
                "st.global.L2::evict_last.v4.b64 [%0], {%1, %2, %3, %4};"
                :: "l"(p), "l"(z64), "l"(z64), "l"(z64), "l"(z64)
                : "memory");
        }
    }

    if (threadIdx.x == 0) {
        asm volatile("cp.async.bulk.wait_group 0;" ::: "memory");
    }
}

// ---------------------------------------------------------------- K2
__global__ void k2_finalize() {
    int i = blockIdx.x * blockDim.x + threadIdx.x;
    if (i < NN) {
        float s = g_rowsum[i];
        g_rowinv[i] = (s == 0.0f) ? 1.0f : (1.0f / s);
        g_rowsum[i] = 0.0f;   // ready for next graph replay
    }
}

// ---------------------------------------------------------------- K3
__global__ __launch_bounds__(256) void k3_scatter(
        const int* __restrict__ rows_s, const int* __restrict__ cols_s,
        const float* __restrict__ vals_s, int Es,
        const int* __restrict__ rows_t, const int* __restrict__ cols_t,
        const float* __restrict__ vals_t, int Et,
        const float* __restrict__ gamma, float* __restrict__ out) {
    const float g = gamma[0];
    const float alpha = 1.0f / (1.0f + expf(-g));
    const float beta = 1.0f - alpha;
    const int tid = blockIdx.x * blockDim.x + threadIdx.x;
    const int stride = gridDim.x * blockDim.x;

    const int n = (Es > Et) ? Es : Et;
    for (int e = tid; e < n; e += stride) {
        int rs = 0, cs = 0;  float vs = 0.0f;
        if (e < Es) {
            rs = __ldg(&rows_s[e]);
            cs = __ldg(&cols_s[e]);
            vs = __ldg(&vals_s[e]);
        }
        int rt = 0, ct = 0;  float vt = 0.0f;
        if (e < Et) {
            rt = __ldg(&rows_t[e]);
            ct = __ldg(&cols_t[e]);
            vt = __ldg(&vals_t[e]);
        }
        float invs = g_rowinv[rs];
        float invt = g_rowinv[rt];
        if (e < Es) atomicAdd(&out[((size_t)rs << 13) + cs], alpha * vs * invs);
        if (e < Et) atomicAdd(&out[((size_t)rt << 13) + ct], beta * vt * invt);
    }
}

// ---------------------------------------------------------------- launch
extern "C" void kernel_launch(void* const* d_in, const int* in_sizes, int n_in,
                              void* d_out, int out_size) {
    const int*   rows_s = (const int*)d_in[0];
    const int*   cols_s = (const int*)d_in[1];
    const float* vals_s = (const float*)d_in[2];
    const int*   rows_t = (const int*)d_in[3];
    const int*   cols_t = (const int*)d_in[4];
    const float* vals_t = (const float*)d_in[5];
    const float* gamma  = (const float*)d_in[6];
    float* out = (float*)d_out;

    const int Es = in_sizes[0];
    const int Et = in_sizes[3];

    // one full resident wave: 148 SMs x 8 blocks of 256 threads
    k1_fill<<<1184, 256>>>(rows_s, vals_s, Es, rows_t, vals_t, Et,
                           gamma, out);

    k2_finalize<<<(NN + 255) / 256, 256>>>();

    k3_scatter<<<1184, 256>>>(rows_s, cols_s, vals_s, Es,
                              rows_t, cols_t, vals_t, Et, gamma, out);
}